// round 14
// baseline (speedup 1.0000x reference)
#include <cuda_runtime.h>
#include <cuda_fp16.h>
#include <cstdint>
#include <math.h>

#define BDIM 2
#define TLEN 2048
#define CDIM 1024
#define NH   16
#define DH   64
#define MROWS (BDIM * TLEN)   // 4096

// Scratch (allocation-free rule: __device__ globals)
__device__ __half g_qh[(size_t)BDIM * NH * TLEN * DH];   // [B,H,T,Dh], d-permuted, prescaled
__device__ __half g_kh[(size_t)BDIM * NH * TLEN * DH];   // [B,H,T,Dh], d-permuted
__device__ __half g_vth[(size_t)BDIM * NH * DH * TLEN];  // [B,H,Dh,T] transposed, key-permuted
__device__ __half g_atth[(size_t)MROWS * CDIM];          // [B,T,C], C-permuted
__device__ __half g_xh[(size_t)MROWS * CDIM];            // k-permuted
__device__ __half g_wh[4][(size_t)CDIM * CDIM];          // k-permuted

// ============================================================================
// helpers
// ============================================================================
__device__ __forceinline__ void mma_f16(float* d, const uint32_t* a,
                                        const uint32_t* b) {
    asm volatile(
        "mma.sync.aligned.m16n8k16.row.col.f32.f16.f16.f32 "
        "{%0,%1,%2,%3}, {%4,%5,%6,%7}, {%8,%9}, {%0,%1,%2,%3};"
        : "+f"(d[0]), "+f"(d[1]), "+f"(d[2]), "+f"(d[3])
        : "r"(a[0]), "r"(a[1]), "r"(a[2]), "r"(a[3]), "r"(b[0]), "r"(b[1]));
}
__device__ __forceinline__ uint32_t packh2(float lo, float hi) {
    __half2 h = __floats2half2_rn(lo, hi);
    return *(uint32_t*)&h;
}
__device__ __forceinline__ uint32_t smem_u32(const void* p) {
    uint32_t a;
    asm("{ .reg .u64 t; cvta.to.shared.u64 t, %1; cvt.u32.u64 %0, t; }"
        : "=r"(a) : "l"(p));
    return a;
}
__device__ __forceinline__ void cp_async16(uint32_t saddr, const void* gptr) {
    asm volatile("cp.async.ca.shared.global [%0], [%1], 16;"
                 :: "r"(saddr), "l"(gptr) : "memory");
}
__device__ __forceinline__ void cp_commit() {
    asm volatile("cp.async.commit_group;" ::: "memory");
}
// permuted position of logical index c within a 16-block
__device__ __forceinline__ int p16(int c) {
    return 2 * (c & 7) - (c & 1) + 2 * (c >> 3);
}

// ============================================================================
// preround: fp16-convert x and weights, k-permuted within 16-blocks
// ============================================================================
__global__ void __launch_bounds__(256) preround_kernel(
    const float* __restrict__ x,  const float* __restrict__ Wq,
    const float* __restrict__ Wk, const float* __restrict__ Wv,
    const float* __restrict__ Wo)
{
    const int t = blockIdx.y;
    const float* src;
    __half* dst;
    int n;
    if (t == 0) { src = x; dst = g_xh; n = MROWS * CDIM / 4; }
    else {
        src = (t == 1) ? Wq : (t == 2) ? Wk : (t == 3) ? Wv : Wo;
        dst = g_wh[t - 1];
        n = CDIM * CDIM / 4;
    }
    int idx = blockIdx.x * 256 + threadIdx.x;
    if (idx < n) {
        float4 v = ((const float4*)src)[idx];
        int f = idx * 4;
        int c = f & 15;
        size_t blk = ((size_t)(f >> 4)) << 3;
        __half2* d2 = (__half2*)dst;
        d2[blk + (c & 7) + (c >> 3)]             = __floats2half2_rn(v.x, v.y);
        d2[blk + ((c + 2) & 7) + ((c + 2) >> 3)] = __floats2half2_rn(v.z, v.w);
    }
}

// ============================================================================
// fp16 m16n8k16 cp.async 3-stage GEMM, pointer-increment addressing.
// ============================================================================
#define BK2 32
#define LDT2H 48
#define STAGES 3
#define NSTEP2 (CDIM / BK2)     // 32
#define GSMEM2 (STAGES * 128 * LDT2H * 2 * 2)   // 73728 B

template <int SCATTER>
__global__ void __launch_bounds__(256, 2) gemm_h_kernel(float* __restrict__ Cout)
{
    extern __shared__ __half smh[];
    const int K = CDIM;
    __half* As = smh;                          // [STAGES][128][LDT2H]
    __half* Ws = smh + STAGES * 128 * LDT2H;

    const __half* Ap = SCATTER ? g_xh : g_atth;
    const __half* W  = g_wh[SCATTER ? blockIdx.z : 3];
    const int z = SCATTER ? blockIdx.z : 3;
    const float oscale = (SCATTER && z == 0) ? 0.125f : 1.0f;

    const int bm0  = blockIdx.y * 128;
    const int bn0  = blockIdx.x * 128;
    const int tid  = threadIdx.x;
    const int lane = tid & 31;
    const int wid  = tid >> 5;
    const int g    = lane >> 2;
    const int tig  = lane & 3;
    const int wm   = (wid & 3) * 32;
    const int wn   = (wid >> 2) * 64;

    // --- precomputed cp.async state ---
    const int r  = tid >> 2;               // 0..63
    const int c  = tid & 3;                // 16B chunk
    const __half* pA0 = Ap + (size_t)(bm0 + r) * K + c * 8;
    const __half* pA1 = Ap + (size_t)(bm0 + r + 64) * K + c * 8;
    const __half* pW0 = W  + (size_t)(bn0 + r) * K + c * 8;
    const __half* pW1 = W  + (size_t)(bn0 + r + 64) * K + c * 8;
    const uint32_t soff0 = (uint32_t)(r * LDT2H + c * 8) * 2;
    const uint32_t soff1 = (uint32_t)((r + 64) * LDT2H + c * 8) * 2;
    uint32_t uA[STAGES], uW[STAGES];
    {
        const uint32_t sbA = smem_u32(As);
        const uint32_t sbW = smem_u32(Ws);
#pragma unroll
        for (int i = 0; i < STAGES; i++) {
            uA[i] = sbA + (uint32_t)i * 128 * LDT2H * 2;
            uW[i] = sbW + (uint32_t)i * 128 * LDT2H * 2;
        }
    }
    // --- precomputed fragment smem bases (per warp/thread, stage 0) ---
    const __half* AbS[STAGES];
    const __half* WbS[STAGES];
#pragma unroll
    for (int i = 0; i < STAGES; i++) {
        AbS[i] = As + i * 128 * LDT2H;
        WbS[i] = Ws + i * 128 * LDT2H;
    }
    const int oA = (wm + g) * LDT2H + 4 * tig;
    const int oB = (wn + g) * LDT2H + 4 * tig;

    float d[2][8][4];
#pragma unroll
    for (int mc = 0; mc < 2; mc++)
#pragma unroll
        for (int nc = 0; nc < 8; nc++)
#pragma unroll
            for (int v = 0; v < 4; v++) d[mc][nc][v] = 0.f;

    auto issue = [&](int slot) {
        cp_async16(uA[slot] + soff0, pA0);
        cp_async16(uA[slot] + soff1, pA1);
        cp_async16(uW[slot] + soff0, pW0);
        cp_async16(uW[slot] + soff1, pW1);
        pA0 += BK2; pA1 += BK2; pW0 += BK2; pW1 += BK2;
        cp_commit();
    };

    issue(0);
    issue(1);

    int st = 0, sti = 2;
    for (int s = 0; s < NSTEP2; s++) {
        if (s + 1 < NSTEP2) asm volatile("cp.async.wait_group 1;" ::: "memory");
        else                asm volatile("cp.async.wait_group 0;" ::: "memory");
        __syncthreads();
        if (s + 2 < NSTEP2) {
            issue(sti);
            sti = (sti + 1 == STAGES) ? 0 : sti + 1;
        }

        const __half* Ab = AbS[st];
        const __half* Wb = WbS[st];
#pragma unroll
        for (int ks = 0; ks < 2; ks++) {
            uint32_t a[2][4];
#pragma unroll
            for (int mc = 0; mc < 2; mc++) {
                uint2 lo = *(const uint2*)&Ab[oA + mc * 16 * LDT2H + ks * 16];
                uint2 hi = *(const uint2*)&Ab[oA + (mc * 16 + 8) * LDT2H + ks * 16];
                a[mc][0] = lo.x; a[mc][1] = hi.x; a[mc][2] = lo.y; a[mc][3] = hi.y;
            }
#pragma unroll
            for (int nc = 0; nc < 8; nc++) {
                uint2 bb = *(const uint2*)&Wb[oB + nc * 8 * LDT2H + ks * 16];
                uint32_t b[2] = {bb.x, bb.y};
                mma_f16(d[0][nc], a[0], b);
                mma_f16(d[1][nc], a[1], b);
            }
        }
        st = (st + 1 == STAGES) ? 0 : st + 1;
    }

#pragma unroll
    for (int mc = 0; mc < 2; mc++) {
#pragma unroll
        for (int nc = 0; nc < 8; nc++) {
            int n = bn0 + wn + nc * 8 + tig * 2;
#pragma unroll
            for (int rr = 0; rr < 2; rr++) {
                int m = bm0 + wm + mc * 16 + g + rr * 8;
                float v0 = d[mc][nc][rr * 2 + 0];
                float v1 = d[mc][nc][rr * 2 + 1];
                if (SCATTER) {
                    v0 *= oscale; v1 *= oscale;
                    int bb = m >> 11;
                    int tt = m & 2047;
                    int hh = n >> 6;
                    int dd = n & 63;                 // even
                    if (z < 2) {
                        __half* base = (z == 0 ? g_qh : g_kh)
                            + (((size_t)bb * NH + hh) * TLEN + tt) * DH;
                        int r16 = dd & 15;
                        ((__half2*)base)[(dd >> 4) * 8 + (r16 & 7) + (r16 >> 3)]
                            = __floats2half2_rn(v0, v1);
                    } else {
                        int tperm = (tt & ~15) + p16(tt & 15);
                        __half* base = g_vth + ((size_t)bb * NH + hh) * DH * TLEN;
                        base[(size_t)dd * TLEN + tperm]       = __float2half_rn(v0);
                        base[(size_t)(dd + 1) * TLEN + tperm] = __float2half_rn(v1);
                    }
                } else {
                    *(float2*)&Cout[(size_t)m * CDIM + n] = make_float2(v0, v1);
                }
            }
        }
    }
}

// ============================================================================
// fp16 m16n8k16 causal flash attention — Q fragments in registers,
// 3-stage cp.async KV ring (wait_group 1), pointer-increment addressing.
// smem: 3 stages x (K 64x80 + V 64x80) halves = 61440 B -> 2 CTAs/SM.
// ============================================================================
#define LDAH 80
#define QROWS 128
#define KVSTAGEH (2 * 64 * LDAH)        // halves per stage = 10240
#define ATT_SMEM (3 * KVSTAGEH * 2)     // 61440 B

__global__ void __launch_bounds__(256, 2) attn_h_kernel()
{
    extern __shared__ __half smh[];
    __half* kvb = smh;                       // [3][ K[64][LDAH] | V[64][LDAH] ]
    const uint32_t skv = smem_u32(kvb);

    const int qt = (gridDim.x - 1) - blockIdx.x;   // big tiles first
    const int bh = blockIdx.y;
    const __half* qg = g_qh + (size_t)bh * TLEN * DH;
    const __half* kg = g_kh + (size_t)bh * TLEN * DH;
    const __half* vg = g_vth + (size_t)bh * DH * TLEN;  // [d][t]

    const int tid  = threadIdx.x;
    const int lane = tid & 31;
    const int wid  = tid >> 5;
    const int g    = lane >> 2;
    const int tig  = lane & 3;

    const int wrow = qt * QROWS + wid * 16;

    // ---- Q fragments: kt-invariant, straight from global to registers ----
    uint32_t qa[4][4];
#pragma unroll
    for (int j = 0; j < 4; j++) {
        uint2 q0 = *(const uint2*)&qg[(size_t)(wrow + g) * DH + 16 * j + 4 * tig];
        uint2 q1 = *(const uint2*)&qg[(size_t)(wrow + g + 8) * DH + 16 * j + 4 * tig];
        qa[j][0] = q0.x; qa[j][1] = q1.x; qa[j][2] = q0.y; qa[j][3] = q1.y;
    }

    // ---- cp.async state (pointer increments) ----
    const int r = tid >> 3;                 // 0..31
    const int c = tid & 7;                  // 16B chunk
    const __half* pK0 = kg + (size_t)r * DH + c * 8;
    const __half* pK1 = kg + (size_t)(r + 32) * DH + c * 8;
    const __half* pV0 = vg + (size_t)r * TLEN + c * 8;
    const __half* pV1 = vg + (size_t)(r + 32) * TLEN + c * 8;
    const uint32_t sKo0 = (uint32_t)(r * LDAH + c * 8) * 2;
    const uint32_t sKo1 = (uint32_t)((r + 32) * LDAH + c * 8) * 2;
    uint32_t skvS[3];
#pragma unroll
    for (int i = 0; i < 3; i++) skvS[i] = skv + (uint32_t)i * KVSTAGEH * 2;

    auto issue_kv = [&](int slot) {
        const uint32_t kb = skvS[slot];
        const uint32_t vb = kb + (uint32_t)(64 * LDAH) * 2;
        cp_async16(kb + sKo0, pK0);
        cp_async16(kb + sKo1, pK1);
        cp_async16(vb + sKo0, pV0);
        cp_async16(vb + sKo1, pV1);
        pK0 += (size_t)64 * DH; pK1 += (size_t)64 * DH;
        pV0 += 64;              pV1 += 64;
        cp_commit();
    };

    const int ktmax = 2 * qt + 1;           // >= 1 always
    issue_kv(0);
    issue_kv(1);

    float mrow0 = -INFINITY, mrow1 = -INFINITY;
    float lrow0 = 0.f, lrow1 = 0.f;
    float o[8][4];
#pragma unroll
    for (int nc = 0; nc < 8; nc++)
#pragma unroll
        for (int v = 0; v < 4; v++) o[nc][v] = 0.f;

    const int oK = g * LDAH + 4 * tig;      // fragment base offset (K and V)

    int st = 0, sti = 2;
    for (int kt = 0; kt <= ktmax; kt++) {
        if (kt < ktmax) asm volatile("cp.async.wait_group 1;" ::: "memory");
        else            asm volatile("cp.async.wait_group 0;" ::: "memory");
        __syncthreads();
        if (kt + 2 <= ktmax) {
            issue_kv(sti);
            sti = (sti + 1 == 3) ? 0 : sti + 1;
        }

        const __half* ks = kvb + st * KVSTAGEH;
        const __half* vs = ks + 64 * LDAH;
        st = (st + 1 == 3) ? 0 : st + 1;

        if (kt * 64 <= wrow + 15) {
            // ---- S = Q K^T ----
            float s[8][4];
#pragma unroll
            for (int nc = 0; nc < 8; nc++)
#pragma unroll
                for (int v = 0; v < 4; v++) s[nc][v] = 0.f;
#pragma unroll
            for (int j = 0; j < 4; j++) {
#pragma unroll
                for (int nc = 0; nc < 8; nc++) {
                    uint2 bk = *(const uint2*)&ks[oK + nc * 8 * LDAH + 16 * j];
                    uint32_t b[2] = {bk.x, bk.y};
                    mma_f16(s[nc], qa[j], b);
                }
            }

            // ---- causal mask ----
            if (kt * 64 + 63 > wrow) {
#pragma unroll
                for (int nc = 0; nc < 8; nc++) {
                    int col = kt * 64 + nc * 8 + 2 * tig;
                    if (col     > wrow + g)     s[nc][0] = -INFINITY;
                    if (col + 1 > wrow + g)     s[nc][1] = -INFINITY;
                    if (col     > wrow + g + 8) s[nc][2] = -INFINITY;
                    if (col + 1 > wrow + g + 8) s[nc][3] = -INFINITY;
                }
            }

            // ---- warp-local online softmax ----
            float t0 = -INFINITY, t1 = -INFINITY;
#pragma unroll
            for (int nc = 0; nc < 8; nc++) {
                t0 = fmaxf(t0, fmaxf(s[nc][0], s[nc][1]));
                t1 = fmaxf(t1, fmaxf(s[nc][2], s[nc][3]));
            }
            t0 = fmaxf(t0, __shfl_xor_sync(0xffffffffu, t0, 1));
            t0 = fmaxf(t0, __shfl_xor_sync(0xffffffffu, t0, 2));
            t1 = fmaxf(t1, __shfl_xor_sync(0xffffffffu, t1, 1));
            t1 = fmaxf(t1, __shfl_xor_sync(0xffffffffu, t1, 2));
            float mn0 = fmaxf(mrow0, t0);
            float mn1 = fmaxf(mrow1, t1);
            float sc0 = __expf(mrow0 - mn0);
            float sc1 = __expf(mrow1 - mn1);
            mrow0 = mn0; mrow1 = mn1;

            float rs0 = 0.f, rs1 = 0.f;
#pragma unroll
            for (int nc = 0; nc < 8; nc++) {
                s[nc][0] = __expf(s[nc][0] - mn0);
                s[nc][1] = __expf(s[nc][1] - mn0);
                s[nc][2] = __expf(s[nc][2] - mn1);
                s[nc][3] = __expf(s[nc][3] - mn1);
                rs0 += s[nc][0] + s[nc][1];
                rs1 += s[nc][2] + s[nc][3];
            }
            rs0 += __shfl_xor_sync(0xffffffffu, rs0, 1);
            rs0 += __shfl_xor_sync(0xffffffffu, rs0, 2);
            rs1 += __shfl_xor_sync(0xffffffffu, rs1, 1);
            rs1 += __shfl_xor_sync(0xffffffffu, rs1, 2);
            lrow0 = lrow0 * sc0 + rs0;
            lrow1 = lrow1 * sc1 + rs1;
#pragma unroll
            for (int nc = 0; nc < 8; nc++) {
                o[nc][0] *= sc0; o[nc][1] *= sc0;
                o[nc][2] *= sc1; o[nc][3] *= sc1;
            }

            // ---- O += P V : A packed from softmax regs, B = V^T LDS.64 ----
#pragma unroll
            for (int j = 0; j < 4; j++) {
                uint32_t a[4];
                a[0] = packh2(s[2 * j][0],     s[2 * j][1]);
                a[1] = packh2(s[2 * j][2],     s[2 * j][3]);
                a[2] = packh2(s[2 * j + 1][0], s[2 * j + 1][1]);
                a[3] = packh2(s[2 * j + 1][2], s[2 * j + 1][3]);
#pragma unroll
                for (int nc = 0; nc < 8; nc++) {
                    uint2 bv = *(const uint2*)&vs[oK + nc * 8 * LDAH + 16 * j];
                    uint32_t b[2] = {bv.x, bv.y};
                    mma_f16(o[nc], a, b);
                }
            }
        }
    }

    // normalize, write g_atth [B,T,C] half, C permuted within 16-blocks
    const int b = bh >> 4;
    const int h = bh & 15;
    const float inv0 = 1.f / lrow0;
    const float inv1 = 1.f / lrow1;
    const int t0r = wrow + g;
    const int t1r = wrow + g + 8;
#pragma unroll
    for (int nc = 0; nc < 8; nc++) {
        int dd  = h * DH + nc * 8 + 2 * tig;    // even
        int r16 = dd & 15;
        int h2i = (dd >> 4) * 8 + (r16 & 7) + (r16 >> 3);
        ((__half2*)&g_atth[((size_t)b * TLEN + t0r) * CDIM])[h2i]
            = __floats2half2_rn(o[nc][0] * inv0, o[nc][1] * inv0);
        ((__half2*)&g_atth[((size_t)b * TLEN + t1r) * CDIM])[h2i]
            = __floats2half2_rn(o[nc][2] * inv1, o[nc][3] * inv1);
    }
}

// ----------------------------------------------------------------------------
extern "C" void kernel_launch(void* const* d_in, const int* in_sizes, int n_in,
                              void* d_out, int out_size)
{
    const float* x  = (const float*)d_in[0];
    const float* Wq = (const float*)d_in[1];
    const float* Wk = (const float*)d_in[2];
    const float* Wv = (const float*)d_in[3];
    const float* Wo = (const float*)d_in[4];
    float* out = (float*)d_out;

    preround_kernel<<<dim3(4096, 5), 256>>>(x, Wq, Wk, Wv, Wo);

    cudaFuncSetAttribute(gemm_h_kernel<1>,
                         cudaFuncAttributeMaxDynamicSharedMemorySize, GSMEM2);
    cudaFuncSetAttribute(gemm_h_kernel<0>,
                         cudaFuncAttributeMaxDynamicSharedMemorySize, GSMEM2);

    gemm_h_kernel<1><<<dim3(CDIM / 128, MROWS / 128, 3), 256, GSMEM2>>>(nullptr);

    cudaFuncSetAttribute(attn_h_kernel,
                         cudaFuncAttributeMaxDynamicSharedMemorySize, ATT_SMEM);
    attn_h_kernel<<<dim3(TLEN / QROWS, BDIM * NH), 256, ATT_SMEM>>>();

    gemm_h_kernel<0><<<dim3(CDIM / 128, MROWS / 128, 1), 256, GSMEM2>>>(out);
}